// round 10
// baseline (speedup 1.0000x reference)
#include <cuda_runtime.h>
#include <cstdint>

// ---------------------------------------------------------------------------
// VectorBasis: out[a,m,o] = sum_{edges e with center a}
//     fc(d_e) * Y_m(e) * sum_n R_n(d_e) * T[sc_a, sn_e, n, o]
// where T[sc,sn,n,o] = sum_q W_alch[sn,q] * emb[sc, n*4+q] * Wc[o, n*4+q]
//
// R10: TWO launches only (pack kernel removed; ~4.2us launch floor saved,
//      edge pays ~+2.7us for int32 species gathers on a 400KB L2-resident
//      table instead of u8/100KB L1-resident).
//   edge      — 4 edges/thread staged loads, scalar Chebyshev,
//               3x red.global.add.v4.f32 into padded (A,12) scratch
//   finalize  — flat zero-writeback: 1 thread per scratch float4-row;
//               writes 3 floats to out, zeroes the row (restores the
//               scratch==0 invariant; g_scratch zero at module load).
// Scratch layout: padded m-rows scratch[a*12 + m*4 + o], lane 3 = pad.
// ---------------------------------------------------------------------------

#define A_MAX 100000
__device__ float g_scratch[A_MAX * 12];

__device__ __forceinline__ void red_add_v4(float* p, float a, float b, float c, float d) {
    asm volatile("red.global.add.v4.f32 [%0], {%1, %2, %3, %4};"
                 :: "l"(p), "f"(a), "f"(b), "f"(c), "f"(d)
                 : "memory");
}

#define EPB 1024   // edges per block (256 threads x 4)

__device__ __forceinline__ void process_edge(
    float vx, float vy, float vz, int a, int nb,
    const int* __restrict__ species,
    const float* __restrict__ sT,
    float* __restrict__ scratch)
{
    float d2   = fmaf(vx, vx, fmaf(vy, vy, vz * vz)) + 1e-12f;
    float invd = rsqrtf(d2);
    float d    = d2 * invd;

    int sc = __ldg(&species[a]);
    int sn = __ldg(&species[nb]);
    const float* T = &sT[(sc * 4 + sn) * 25];

    // R_n = sin(n*pi*d/rc)/d via scalar Chebyshev recurrence
    float s, c;
    __sincosf(0.62831853071795864769f * d, &s, &c);  // pi/5 * d
    float twoc = 2.0f * c;
    float r_nm1 = 0.0f;
    float r_n   = s * invd;

    float h0 = 0.f, h1 = 0.f, h2 = 0.f;
#pragma unroll
    for (int n = 0; n < 8; n++) {
        h0 = fmaf(r_n, T[n * 3 + 0], h0);
        h1 = fmaf(r_n, T[n * 3 + 1], h1);
        h2 = fmaf(r_n, T[n * 3 + 2], h2);
        float r_np1 = fmaf(twoc, r_n, -r_nm1);
        r_nm1 = r_n;
        r_n   = r_np1;
    }

    // shifted-cosine cutoff (rc=5, width=0.5)
    float fc;
    if (d < 4.5f) {
        fc = 1.0f;
    } else if (d < 5.0f) {
        fc = 0.5f * (__cosf(6.28318530717958647692f * (d - 4.5f)) + 1.0f);
    } else {
        fc = 0.0f;
    }

    float f  = fc * invd;
    float y0 = vy * f;   // m order (-1,0,1) -> (y,z,x)/d
    float y1 = vz * f;
    float y2 = vx * f;

    // padded m-row layout: rows m at +0,+4,+8; lane 3 = pad
    float* base = scratch + (size_t)a * 12;
    red_add_v4(base + 0, y0 * h0, y0 * h1, y0 * h2, 0.0f);
    red_add_v4(base + 4, y1 * h0, y1 * h1, y1 * h2, 0.0f);
    red_add_v4(base + 8, y2 * h0, y2 * h1, y2 * h2, 0.0f);
}

__global__ void __launch_bounds__(256)
edge_kernel(const float* __restrict__ vecs,     // (E,3)
            const int*   __restrict__ centers,  // (E,)
            const int*   __restrict__ neighbors,// (E,)
            const int*   __restrict__ species,  // (A,) int32, gathered direct
            const float* __restrict__ W_alch,   // (4,4)
            const float* __restrict__ emb,      // (4,32)
            const float* __restrict__ Wc,       // (3,32)
            float*       __restrict__ scratch,  // (A,12)
            int E)
{
    // Per-species-pair contraction table, stride 25 (odd -> conflict-free).
    __shared__ float sT[16 * 25];
    __shared__ float sV[EPB * 3];   // 12 KB staged vectors

    for (int t = threadIdx.x; t < 16 * 24; t += blockDim.x) {
        int p = t / 24, r = t - p * 24;
        int n = r / 3,  o = r - n * 3;
        int sc = p >> 2, sn = p & 3;
        float v = 0.f;
#pragma unroll
        for (int q = 0; q < 4; q++) {
            int d = n * 4 + q;
            v = fmaf(W_alch[sn * 4 + q] * emb[sc * 32 + d], Wc[o * 32 + d], v);
        }
        sT[p * 25 + r] = v;
    }

    int e0   = blockIdx.x * EPB;
    bool full = (e0 + EPB <= E);
    int t = threadIdx.x;

    if (full) {
        const float4* v4 = (const float4*)(vecs + (size_t)e0 * 3);
#pragma unroll
        for (int k = 0; k < 3; k++)
            ((float4*)sV)[t + 256 * k] = v4[t + 256 * k];
    }
    __syncthreads();

    int base = e0 + t * 4;
    if (full) {
        int4 cc = *(const int4*)(centers   + base);
        int4 nn = *(const int4*)(neighbors + base);
        float4 va = ((const float4*)sV)[t * 3 + 0];
        float4 vb = ((const float4*)sV)[t * 3 + 1];
        float4 vc = ((const float4*)sV)[t * 3 + 2];
        process_edge(va.x, va.y, va.z, cc.x, nn.x, species, sT, scratch);
        process_edge(va.w, vb.x, vb.y, cc.y, nn.y, species, sT, scratch);
        process_edge(vb.z, vb.w, vc.x, cc.z, nn.z, species, sT, scratch);
        process_edge(vc.y, vc.z, vc.w, cc.w, nn.w, species, sT, scratch);
    } else {
#pragma unroll
        for (int j = 0; j < 4; j++) {
            int e = base + j;
            if (e < E) {
                float vx = vecs[(size_t)e * 3 + 0];
                float vy = vecs[(size_t)e * 3 + 1];
                float vz = vecs[(size_t)e * 3 + 2];
                process_edge(vx, vy, vz, centers[e], neighbors[e], species, sT, scratch);
            }
        }
    }
}

// Flat finalize + zero-writeback: thread i owns scratch float4-row i
// (atom a = i/3, row m = i%3). Reads [h0,h1,h2,pad], writes 3 floats to
// out[a*9 + m*3 .. +2], zeroes the row.
__global__ void __launch_bounds__(256)
finalize_kernel(float4* __restrict__ scratch4, float* __restrict__ out, int nrows)
{
    int i = blockIdx.x * blockDim.x + threadIdx.x;
    if (i >= nrows) return;
    float4 v = scratch4[i];
    int a = i / 3;
    int m = i - a * 3;
    float* o = out + (size_t)a * 9 + m * 3;
    o[0] = v.x;
    o[1] = v.y;
    o[2] = v.z;
    scratch4[i] = make_float4(0.f, 0.f, 0.f, 0.f);
}

extern "C" void kernel_launch(void* const* d_in, const int* in_sizes, int n_in,
                              void* d_out, int out_size)
{
    const float* vecs      = (const float*)d_in[0];
    const int*   centers   = (const int*)  d_in[1];
    const int*   neighbors = (const int*)  d_in[2];
    const int*   species   = (const int*)  d_in[3];
    // d_in[4], d_in[5] unused by reference
    const float* W_alch    = (const float*)d_in[6];
    const float* emb       = (const float*)d_in[7];
    const float* Wc        = (const float*)d_in[8];

    int E = in_sizes[1];
    int A = in_sizes[3];

    float* scratch = nullptr;
    cudaGetSymbolAddress((void**)&scratch, g_scratch);

    int eblocks = (E + EPB - 1) / EPB;
    edge_kernel<<<eblocks, 256>>>(vecs, centers, neighbors, species,
                                  W_alch, emb, Wc, scratch, E);

    int nrows = A * 3;
    finalize_kernel<<<(nrows + 255) / 256, 256>>>((float4*)scratch, (float*)d_out, nrows);
}

// round 11
// speedup vs baseline: 1.0632x; 1.0632x over previous
#include <cuda_runtime.h>
#include <cstdint>

// ---------------------------------------------------------------------------
// VectorBasis: out[a,m,o] = sum_{edges e with center a}
//     fc(d_e) * Y_m(e) * sum_n R_n(d_e) * T[sc_a, sn_e, n, o]
// where T[sc,sn,n,o] = sum_q W_alch[sn,q] * emb[sc, n*4+q] * Wc[o, n*4+q]
//
// R11 = R9 pipeline (pack u8 -> edge_4x -> finalize_wb) + programmatic
//       dependent launch (PDL) so launch slots overlap:
//   edge:     PSS secondary of pack; builds sT + stages vecs BEFORE
//             cudaGridDependencySynchronize(), then gathers spec8.
//   finalize: PSS secondary of edge; grid-syncs before reading scratch.
//   edge triggers completion right after issuing its REDs.
// Scratch layout: padded m-rows scratch[a*12 + m*4 + o], lane 3 = pad.
// g_scratch zero at module load; finalize zero-writeback restores invariant.
// ---------------------------------------------------------------------------

#define A_MAX 100000
__device__ float         g_scratch[A_MAX * 12];
__device__ unsigned char g_spec8[A_MAX + 4];

__device__ __forceinline__ void red_add_v4(float* p, float a, float b, float c, float d) {
    asm volatile("red.global.add.v4.f32 [%0], {%1, %2, %3, %4};"
                 :: "l"(p), "f"(a), "f"(b), "f"(c), "f"(d)
                 : "memory");
}

// species int32 -> u8 pack (vectorized).
__global__ void __launch_bounds__(256)
pack_kernel(const int4* __restrict__ species4, const int* __restrict__ species,
            uchar4* __restrict__ spec8_4, unsigned char* __restrict__ spec8, int A)
{
    int i = blockIdx.x * blockDim.x + threadIdx.x;
    int np = A >> 2;
    if (i < np) {
        int4 s = species4[i];
        spec8_4[i] = make_uchar4((unsigned char)s.x, (unsigned char)s.y,
                                 (unsigned char)s.z, (unsigned char)s.w);
    }
    if (i == np) {
        for (int j = np * 4; j < A; j++) spec8[j] = (unsigned char)species[j];
    }
}

#define EPB 1024   // edges per block (256 threads x 4)

__device__ __forceinline__ void process_edge(
    float vx, float vy, float vz, int a, int nb,
    const unsigned char* __restrict__ spec8,
    const float* __restrict__ sT,
    float* __restrict__ scratch)
{
    float d2   = fmaf(vx, vx, fmaf(vy, vy, vz * vz)) + 1e-12f;
    float invd = rsqrtf(d2);
    float d    = d2 * invd;

    int sc = (int)__ldg(&spec8[a]);
    int sn = (int)__ldg(&spec8[nb]);
    const float* T = &sT[(sc * 4 + sn) * 25];

    // R_n = sin(n*pi*d/rc)/d via scalar Chebyshev recurrence
    float s, c;
    __sincosf(0.62831853071795864769f * d, &s, &c);  // pi/5 * d
    float twoc = 2.0f * c;
    float r_nm1 = 0.0f;
    float r_n   = s * invd;

    float h0 = 0.f, h1 = 0.f, h2 = 0.f;
#pragma unroll
    for (int n = 0; n < 8; n++) {
        h0 = fmaf(r_n, T[n * 3 + 0], h0);
        h1 = fmaf(r_n, T[n * 3 + 1], h1);
        h2 = fmaf(r_n, T[n * 3 + 2], h2);
        float r_np1 = fmaf(twoc, r_n, -r_nm1);
        r_nm1 = r_n;
        r_n   = r_np1;
    }

    // shifted-cosine cutoff (rc=5, width=0.5)
    float fc;
    if (d < 4.5f) {
        fc = 1.0f;
    } else if (d < 5.0f) {
        fc = 0.5f * (__cosf(6.28318530717958647692f * (d - 4.5f)) + 1.0f);
    } else {
        fc = 0.0f;
    }

    float f  = fc * invd;
    float y0 = vy * f;   // m order (-1,0,1) -> (y,z,x)/d
    float y1 = vz * f;
    float y2 = vx * f;

    // padded m-row layout: rows m at +0,+4,+8; lane 3 = pad
    float* base = scratch + (size_t)a * 12;
    red_add_v4(base + 0, y0 * h0, y0 * h1, y0 * h2, 0.0f);
    red_add_v4(base + 4, y1 * h0, y1 * h1, y1 * h2, 0.0f);
    red_add_v4(base + 8, y2 * h0, y2 * h1, y2 * h2, 0.0f);
}

__global__ void __launch_bounds__(256)
edge_kernel(const float*         __restrict__ vecs,     // (E,3)
            const int*           __restrict__ centers,  // (E,)
            const int*           __restrict__ neighbors,// (E,)
            const unsigned char* __restrict__ spec8,    // (A,) packed
            const float*         __restrict__ W_alch,   // (4,4)
            const float*         __restrict__ emb,      // (4,32)
            const float*         __restrict__ Wc,       // (3,32)
            float*               __restrict__ scratch,  // (A,12)
            int E)
{
    // Per-species-pair contraction table, stride 25 (odd -> conflict-free).
    __shared__ float sT[16 * 25];
    __shared__ float sV[EPB * 3];   // 12 KB staged vectors

    // ---- independent preamble (no spec8 dependency) ----
    for (int t = threadIdx.x; t < 16 * 24; t += blockDim.x) {
        int p = t / 24, r = t - p * 24;
        int n = r / 3,  o = r - n * 3;
        int sc = p >> 2, sn = p & 3;
        float v = 0.f;
#pragma unroll
        for (int q = 0; q < 4; q++) {
            int d = n * 4 + q;
            v = fmaf(W_alch[sn * 4 + q] * emb[sc * 32 + d], Wc[o * 32 + d], v);
        }
        sT[p * 25 + r] = v;
    }

    int e0   = blockIdx.x * EPB;
    bool full = (e0 + EPB <= E);
    int t = threadIdx.x;

    if (full) {
        const float4* v4 = (const float4*)(vecs + (size_t)e0 * 3);
#pragma unroll
        for (int k = 0; k < 3; k++)
            ((float4*)sV)[t + 256 * k] = v4[t + 256 * k];
    }
    __syncthreads();

    // ---- wait for pack_kernel's spec8 writes ----
    cudaGridDependencySynchronize();

    int base = e0 + t * 4;
    if (full) {
        int4 cc = *(const int4*)(centers   + base);
        int4 nn = *(const int4*)(neighbors + base);
        float4 va = ((const float4*)sV)[t * 3 + 0];
        float4 vb = ((const float4*)sV)[t * 3 + 1];
        float4 vc = ((const float4*)sV)[t * 3 + 2];
        process_edge(va.x, va.y, va.z, cc.x, nn.x, spec8, sT, scratch);
        process_edge(va.w, vb.x, vb.y, cc.y, nn.y, spec8, sT, scratch);
        process_edge(vb.z, vb.w, vc.x, cc.z, nn.z, spec8, sT, scratch);
        process_edge(vc.y, vc.z, vc.w, cc.w, nn.w, spec8, sT, scratch);
    } else {
#pragma unroll
        for (int j = 0; j < 4; j++) {
            int e = base + j;
            if (e < E) {
                float vx = vecs[(size_t)e * 3 + 0];
                float vy = vecs[(size_t)e * 3 + 1];
                float vz = vecs[(size_t)e * 3 + 2];
                process_edge(vx, vy, vz, centers[e], neighbors[e], spec8, sT, scratch);
            }
        }
    }

    // allow finalize to begin launching (it grid-syncs before reading scratch)
    cudaTriggerProgrammaticLaunchCompletion();
}

// Flat finalize + zero-writeback: thread i owns scratch float4-row i
// (atom a = i/3, row m = i%3).
__global__ void __launch_bounds__(256)
finalize_kernel(float4* __restrict__ scratch4, float* __restrict__ out, int nrows)
{
    int i = blockIdx.x * blockDim.x + threadIdx.x;
    int a = i / 3;
    int m = i - a * 3;

    // wait for ALL edge_kernel REDs to be visible
    cudaGridDependencySynchronize();

    if (i >= nrows) return;
    float4 v = scratch4[i];
    float* o = out + (size_t)a * 9 + m * 3;
    o[0] = v.x;
    o[1] = v.y;
    o[2] = v.z;
    scratch4[i] = make_float4(0.f, 0.f, 0.f, 0.f);
}

extern "C" void kernel_launch(void* const* d_in, const int* in_sizes, int n_in,
                              void* d_out, int out_size)
{
    const float* vecs      = (const float*)d_in[0];
    const int*   centers   = (const int*)  d_in[1];
    const int*   neighbors = (const int*)  d_in[2];
    const int*   species   = (const int*)  d_in[3];
    // d_in[4], d_in[5] unused by reference
    const float* W_alch    = (const float*)d_in[6];
    const float* emb       = (const float*)d_in[7];
    const float* Wc        = (const float*)d_in[8];

    int E = in_sizes[1];
    int A = in_sizes[3];

    float* scratch = nullptr;
    cudaGetSymbolAddress((void**)&scratch, g_scratch);
    unsigned char* spec8 = nullptr;
    cudaGetSymbolAddress((void**)&spec8, g_spec8);

    // 1) pack (normal launch)
    int pn = (A >> 2) + 1;
    pack_kernel<<<(pn + 255) / 256, 256>>>((const int4*)species, species,
                                           (uchar4*)spec8, spec8, A);

    // PDL attribute shared by the two secondary launches
    cudaLaunchAttribute attrs[1];
    attrs[0].id = cudaLaunchAttributeProgrammaticStreamSerialization;
    attrs[0].val.programmaticStreamSerializationAllowed = 1;

    // 2) edge (PSS secondary of pack)
    {
        cudaLaunchConfig_t cfg = {};
        cfg.gridDim  = dim3((E + EPB - 1) / EPB);
        cfg.blockDim = dim3(256);
        cfg.dynamicSmemBytes = 0;
        cfg.stream = 0;
        cfg.attrs = attrs;
        cfg.numAttrs = 1;
        cudaLaunchKernelEx(&cfg, edge_kernel, vecs, centers, neighbors,
                           (const unsigned char*)spec8, W_alch, emb, Wc,
                           scratch, E);
    }

    // 3) finalize (PSS secondary of edge)
    {
        int nrows = A * 3;
        cudaLaunchConfig_t cfg = {};
        cfg.gridDim  = dim3((nrows + 255) / 256);
        cfg.blockDim = dim3(256);
        cfg.dynamicSmemBytes = 0;
        cfg.stream = 0;
        cfg.attrs = attrs;
        cfg.numAttrs = 1;
        cudaLaunchKernelEx(&cfg, finalize_kernel, (float4*)scratch,
                           (float*)d_out, nrows);
    }
}

// round 12
// speedup vs baseline: 1.1378x; 1.0702x over previous
#include <cuda_runtime.h>
#include <cstdint>

// ---------------------------------------------------------------------------
// VectorBasis: out[a,m,o] = sum_{edges e with center a}
//     fc(d_e) * Y_m(e) * sum_n R_n(d_e) * T[sc_a, sn_e, n, o]
// where T[sc,sn,n,o] = sum_q W_alch[sn,q] * emb[sc, n*4+q] * Wc[o, n*4+q]
//
// R12 = R9 with the edge kernel's smem vector staging removed:
//   direct per-thread LDG.128 x3 of vecs (sector-optimal for the
//   4-edge/thread layout), one less __syncthreads, 12KB less smem ->
//   more latency-hiding headroom for the RED/gather traffic.
// Pipeline: pack(u8) -> edge_4x -> finalize_wb (all previously proven).
// Scratch layout: padded m-rows scratch[a*12 + m*4 + o], lane 3 = pad.
// g_scratch zero at module load; finalize zero-writeback restores invariant.
// ---------------------------------------------------------------------------

#define A_MAX 100000
__device__ float         g_scratch[A_MAX * 12];
__device__ unsigned char g_spec8[A_MAX + 4];

__device__ __forceinline__ void red_add_v4(float* p, float a, float b, float c, float d) {
    asm volatile("red.global.add.v4.f32 [%0], {%1, %2, %3, %4};"
                 :: "l"(p), "f"(a), "f"(b), "f"(c), "f"(d)
                 : "memory");
}

// species int32 -> u8 pack (vectorized).
__global__ void __launch_bounds__(256)
pack_kernel(const int4* __restrict__ species4, const int* __restrict__ species,
            uchar4* __restrict__ spec8_4, unsigned char* __restrict__ spec8, int A)
{
    int i = blockIdx.x * blockDim.x + threadIdx.x;
    int np = A >> 2;
    if (i < np) {
        int4 s = species4[i];
        spec8_4[i] = make_uchar4((unsigned char)s.x, (unsigned char)s.y,
                                 (unsigned char)s.z, (unsigned char)s.w);
    }
    if (i == np) {
        for (int j = np * 4; j < A; j++) spec8[j] = (unsigned char)species[j];
    }
}

#define EPB 1024   // edges per block (256 threads x 4)

__device__ __forceinline__ void process_edge(
    float vx, float vy, float vz, int a, int nb,
    const unsigned char* __restrict__ spec8,
    const float* __restrict__ sT,
    float* __restrict__ scratch)
{
    float d2   = fmaf(vx, vx, fmaf(vy, vy, vz * vz)) + 1e-12f;
    float invd = rsqrtf(d2);
    float d    = d2 * invd;

    int sc = (int)__ldg(&spec8[a]);
    int sn = (int)__ldg(&spec8[nb]);
    const float* T = &sT[(sc * 4 + sn) * 25];

    // R_n = sin(n*pi*d/rc)/d via scalar Chebyshev recurrence
    float s, c;
    __sincosf(0.62831853071795864769f * d, &s, &c);  // pi/5 * d
    float twoc = 2.0f * c;
    float r_nm1 = 0.0f;
    float r_n   = s * invd;

    float h0 = 0.f, h1 = 0.f, h2 = 0.f;
#pragma unroll
    for (int n = 0; n < 8; n++) {
        h0 = fmaf(r_n, T[n * 3 + 0], h0);
        h1 = fmaf(r_n, T[n * 3 + 1], h1);
        h2 = fmaf(r_n, T[n * 3 + 2], h2);
        float r_np1 = fmaf(twoc, r_n, -r_nm1);
        r_nm1 = r_n;
        r_n   = r_np1;
    }

    // shifted-cosine cutoff (rc=5, width=0.5)
    float fc;
    if (d < 4.5f) {
        fc = 1.0f;
    } else if (d < 5.0f) {
        fc = 0.5f * (__cosf(6.28318530717958647692f * (d - 4.5f)) + 1.0f);
    } else {
        fc = 0.0f;
    }

    float f  = fc * invd;
    float y0 = vy * f;   // m order (-1,0,1) -> (y,z,x)/d
    float y1 = vz * f;
    float y2 = vx * f;

    // padded m-row layout: rows m at +0,+4,+8; lane 3 = pad
    float* base = scratch + (size_t)a * 12;
    red_add_v4(base + 0, y0 * h0, y0 * h1, y0 * h2, 0.0f);
    red_add_v4(base + 4, y1 * h0, y1 * h1, y1 * h2, 0.0f);
    red_add_v4(base + 8, y2 * h0, y2 * h1, y2 * h2, 0.0f);
}

__global__ void __launch_bounds__(256)
edge_kernel(const float*         __restrict__ vecs,     // (E,3)
            const int*           __restrict__ centers,  // (E,)
            const int*           __restrict__ neighbors,// (E,)
            const unsigned char* __restrict__ spec8,    // (A,) packed
            const float*         __restrict__ W_alch,   // (4,4)
            const float*         __restrict__ emb,      // (4,32)
            const float*         __restrict__ Wc,       // (3,32)
            float*               __restrict__ scratch,  // (A,12)
            int E)
{
    // Per-species-pair contraction table, stride 25 (odd -> conflict-free).
    __shared__ float sT[16 * 25];
    {
        int t = threadIdx.x;
        if (t < 192) {
            // 16 pairs x 12 entries... build with 192 threads, 2 entries each
            int idx0 = t * 2;
#pragma unroll
            for (int u = 0; u < 2; u++) {
                int idx = idx0 + u;            // 0..383 = 16*24
                int p = idx / 24, r = idx - p * 24;
                int n = r / 3,  o = r - n * 3;
                int sc = p >> 2, sn = p & 3;
                float v = 0.f;
#pragma unroll
                for (int q = 0; q < 4; q++) {
                    int dd = n * 4 + q;
                    v = fmaf(W_alch[sn * 4 + q] * emb[sc * 32 + dd], Wc[o * 32 + dd], v);
                }
                sT[p * 25 + r] = v;
            }
        }
    }
    __syncthreads();

    int e0 = blockIdx.x * EPB;
    int t  = threadIdx.x;
    int base = e0 + t * 4;

    if (e0 + EPB <= E) {
        // direct vectorized loads: thread t owns edges [base, base+4)
        const float4* v4 = (const float4*)(vecs + (size_t)e0 * 3);
        float4 va = v4[t * 3 + 0];
        float4 vb = v4[t * 3 + 1];
        float4 vc = v4[t * 3 + 2];
        int4 cc = *(const int4*)(centers   + base);
        int4 nn = *(const int4*)(neighbors + base);
        process_edge(va.x, va.y, va.z, cc.x, nn.x, spec8, sT, scratch);
        process_edge(va.w, vb.x, vb.y, cc.y, nn.y, spec8, sT, scratch);
        process_edge(vb.z, vb.w, vc.x, cc.z, nn.z, spec8, sT, scratch);
        process_edge(vc.y, vc.z, vc.w, cc.w, nn.w, spec8, sT, scratch);
    } else {
#pragma unroll
        for (int j = 0; j < 4; j++) {
            int e = base + j;
            if (e < E) {
                float vx = vecs[(size_t)e * 3 + 0];
                float vy = vecs[(size_t)e * 3 + 1];
                float vz = vecs[(size_t)e * 3 + 2];
                process_edge(vx, vy, vz, centers[e], neighbors[e], spec8, sT, scratch);
            }
        }
    }
}

// Flat finalize + zero-writeback: thread i owns scratch float4-row i
// (atom a = i/3, row m = i%3). Reads [h0,h1,h2,pad], writes 3 floats to
// out[a*9 + m*3 .. +2], zeroes the row.
__global__ void __launch_bounds__(256)
finalize_kernel(float4* __restrict__ scratch4, float* __restrict__ out, int nrows)
{
    int i = blockIdx.x * blockDim.x + threadIdx.x;
    if (i >= nrows) return;
    float4 v = scratch4[i];
    int a = i / 3;
    int m = i - a * 3;
    float* o = out + (size_t)a * 9 + m * 3;
    o[0] = v.x;
    o[1] = v.y;
    o[2] = v.z;
    scratch4[i] = make_float4(0.f, 0.f, 0.f, 0.f);
}

extern "C" void kernel_launch(void* const* d_in, const int* in_sizes, int n_in,
                              void* d_out, int out_size)
{
    const float* vecs      = (const float*)d_in[0];
    const int*   centers   = (const int*)  d_in[1];
    const int*   neighbors = (const int*)  d_in[2];
    const int*   species   = (const int*)  d_in[3];
    // d_in[4], d_in[5] unused by reference
    const float* W_alch    = (const float*)d_in[6];
    const float* emb       = (const float*)d_in[7];
    const float* Wc        = (const float*)d_in[8];

    int E = in_sizes[1];
    int A = in_sizes[3];

    float* scratch = nullptr;
    cudaGetSymbolAddress((void**)&scratch, g_scratch);
    unsigned char* spec8 = nullptr;
    cudaGetSymbolAddress((void**)&spec8, g_spec8);

    int pn = (A >> 2) + 1;
    pack_kernel<<<(pn + 255) / 256, 256>>>((const int4*)species, species,
                                           (uchar4*)spec8, spec8, A);

    int eblocks = (E + EPB - 1) / EPB;
    edge_kernel<<<eblocks, 256>>>(vecs, centers, neighbors, spec8,
                                  W_alch, emb, Wc, scratch, E);

    int nrows = A * 3;
    finalize_kernel<<<(nrows + 255) / 256, 256>>>((float4*)scratch, (float*)d_out, nrows);
}